// round 13
// baseline (speedup 1.0000x reference)
#include <cuda_runtime.h>
#include <cuda_fp16.h>

#define Bc 2
#define Lc 2048
#define Hc 8
#define Dc 64
#define HD 512              // floats per sequence position (H*D)
#define CHUNK 16
#define NCHUNK 128          // Lc / CHUNK
#define NE (Bc*Lc*Hc*Dc)    // 2,097,152 elements

// Scratch (device globals — no allocation allowed)
__device__ float  g_chunk[Bc*NCHUNK*HD];        // exclusive prefix over chunks
__device__ float  g_cpartA[Bc*NCHUNK*HD];       // half-chunk partial sums (pos 0-7)
__device__ float  g_cpartB[Bc*NCHUNK*HD];       // half-chunk partial sums (pos 8-15)
__device__ __half g_kh[NE];                     // fp16 shadow of K (row = 128B = 1 line)
__device__ __half g_vh[NE];                     // fp16 shadow of V

// ---------------- Pre-pass: V convert + half-chunk sums, K convert (MLP4) ----

__global__ void prepass(const float* __restrict__ K, const float* __restrict__ V) {
    if (blockIdx.x < 512) {
        // block = (b, chunk c, half h): 8 positions x 128 float4 columns.
        // thread: col = tid&127, sub = tid>>7 -> 4 positions each (MLP=4).
        int b = blockIdx.x >> 8;
        int c = (blockIdx.x >> 1) & 127;
        int h = blockIdx.x & 1;
        int col = threadIdx.x & 127;
        int sub = threadIdx.x >> 7;
        int p0 = c*CHUNK + h*8 + sub*4;
        const float4* V4 = (const float4*)V;
        uint2* vh = (uint2*)g_vh;
        int idx0 = (b*Lc + p0)*128 + col;
        float4 v0 = V4[idx0];
        float4 v1 = V4[idx0 + 128];
        float4 v2 = V4[idx0 + 256];
        float4 v3 = V4[idx0 + 384];
        #define CVT_STV(VV, OFF) { \
            __half2 h0 = __floats2half2_rn(VV.x, VV.y); \
            __half2 h1 = __floats2half2_rn(VV.z, VV.w); \
            uint2 uu; uu.x = *(unsigned*)&h0; uu.y = *(unsigned*)&h1; \
            vh[idx0 + (OFF)] = uu; }
        CVT_STV(v0, 0) CVT_STV(v1, 128) CVT_STV(v2, 256) CVT_STV(v3, 384)
        #undef CVT_STV
        float4 s;
        s.x = (v0.x+v1.x)+(v2.x+v3.x);
        s.y = (v0.y+v1.y)+(v2.y+v3.y);
        s.z = (v0.z+v1.z)+(v2.z+v3.z);
        s.w = (v0.w+v1.w)+(v2.w+v3.w);
        __shared__ float4 sm[128];
        if (sub) sm[col] = s;
        __syncthreads();
        if (!sub) {
            float4 o = sm[col];
            s.x += o.x; s.y += o.y; s.z += o.z; s.w += o.w;
            float* dst = h ? g_cpartB : g_cpartA;
            ((float4*)dst)[(b*NCHUNK + c)*128 + col] = s;
        }
    } else {
        // K fp16 shadow, 4 float4 per thread (MLP=4)
        int t4 = (blockIdx.x - 512)*256 + threadIdx.x;   // 0..131071
        const float4* K4 = (const float4*)K;
        uint2* kh = (uint2*)g_kh;
        float4 k0 = K4[t4];
        float4 k1 = K4[t4 + 131072];
        float4 k2 = K4[t4 + 262144];
        float4 k3 = K4[t4 + 393216];
        #define CVT_ST(KK, OFF) { \
            __half2 h0 = __floats2half2_rn(KK.x, KK.y); \
            __half2 h1 = __floats2half2_rn(KK.z, KK.w); \
            uint2 uu; uu.x = *(unsigned*)&h0; uu.y = *(unsigned*)&h1; \
            kh[t4 + (OFF)] = uu; }
        CVT_ST(k0, 0) CVT_ST(k1, 131072) CVT_ST(k2, 262144) CVT_ST(k3, 393216)
        #undef CVT_ST
    }
}

// Exclusive scan over 128 chunks per (b, dim512), merging the two halves.
__global__ void scan_chunks() {
    int idx = blockIdx.x*256 + threadIdx.x;
    int b = idx >> 9, d = idx & 511;
    float run = 0.f;
    #pragma unroll 8
    for (int c = 0; c < NCHUNK; ++c) {
        int p = (b*NCHUNK + c)*HD + d;
        float t = g_cpartA[p] + g_cpartB[p];
        g_chunk[p] = run;                     // exclusive prefix (fp32 exact)
        run += t;
    }
}

// ---------------- Main sparse-attention kernel -------------------------------
// One warp per output row i (max parallelism: 32768 warps). 4 key groups x
// 8 lanes; lane owns one 16B uint4 of the 128B fp16 row. Dot in fp16
// (HMUL2/HFMA2), 3-shuffle butterfly over the 8-lane group; V accumulated in
// fp16 HFMA2 (single set). __launch_bounds__(256, 8) caps regs at 32 ->
// 8 blocks/SM (100% theoretical occupancy) to hide load/shuffle latency.
// Prefix trick v2: local keys j >= cbase (= i & ~15) use e^x instead of
// e^x - 1; denominator = accw + cbase; fp32 chunk prefix added in epilogue.

__device__ __forceinline__ __half2 shx2(__half2 v, int m) {
    unsigned u = *reinterpret_cast<unsigned*>(&v);
    u = __shfl_xor_sync(0xffffffffu, u, m);
    return *reinterpret_cast<__half2*>(&u);
}

#define PAIR_BODY(J, VAL, SUB)                                                \
{                                                                             \
    uint4 ku = KH[base_u4 + (J)*64];                                          \
    uint4 vu = VH[base_u4 + (J)*64];                                          \
    __half2 sA = __hmul2(qh0, *(const __half2*)&ku.x);                        \
    sA = __hfma2(qh1, *(const __half2*)&ku.y, sA);                            \
    __half2 sB = __hmul2(qh2, *(const __half2*)&ku.z);                        \
    sB = __hfma2(qh3, *(const __half2*)&ku.w, sB);                            \
    float2 sf = __half22float2(__hadd2(sA, sB));                              \
    float xp = sf.x + sf.y;                                                   \
    xp += __shfl_xor_sync(0xffffffffu, xp, 1);                                \
    xp += __shfl_xor_sync(0xffffffffu, xp, 2);                                \
    xp += __shfl_xor_sync(0xffffffffu, xp, 4);                                \
    float w = (VAL) ? (__expf(0.125f*xp) - (SUB)) : 0.f;                      \
    accw += w;                                                                \
    __half2 wh = __float2half2_rn(w);                                         \
    a0 = __hfma2(wh, *(const __half2*)&vu.x, a0);                             \
    a1 = __hfma2(wh, *(const __half2*)&vu.y, a1);                             \
    a2 = __hfma2(wh, *(const __half2*)&vu.z, a2);                             \
    a3 = __hfma2(wh, *(const __half2*)&vu.w, a3);                             \
}

__global__ __launch_bounds__(256, 8)
void dozer_main(const float* __restrict__ Q, float* __restrict__ O) {
    const int lane = threadIdx.x & 31;
    const int g    = lane >> 3;               // key group (0..3)
    const int l8   = lane & 7;                // 16B dim slice within row

    // balance remap: warps of one block spread across the whole row range
    int gw = (threadIdx.x >> 5)*4096 + blockIdx.x;
    int bh = gw >> 11;
    int i  = gw & 2047;
    int base_f  = (bh>>3)*(Lc*HD) + (bh&7)*Dc;
    int base_u4 = (base_f >> 3) + l8;            // uint4 index into half arrays
    int qoff4   = (base_f >> 2) + i*128 + 2*l8;  // float4 index of lane's 8 dims

    const uint4* __restrict__ KH = (const uint4*)g_kh;
    const uint4* __restrict__ VH = (const uint4*)g_vh;

    float4 qa = ((const float4*)Q)[qoff4];
    float4 qb = ((const float4*)Q)[qoff4 + 1];
    const __half2 qh0 = __floats2half2_rn(qa.x, qa.y);
    const __half2 qh1 = __floats2half2_rn(qa.z, qa.w);
    const __half2 qh2 = __floats2half2_rn(qb.x, qb.y);
    const __half2 qh3 = __floats2half2_rn(qb.z, qb.w);

    const __half2 hz = __float2half2_rn(0.f);
    __half2 a0 = hz, a1 = hz, a2 = hz, a3 = hz;
    float accw = 0.f;

    const int cbase = i & ~15;                 // chunk start row

    // ---- local band ----
    if (i >= 16) {
        const int lo = i - 16;                 // 17 keys: 5 batches of 4
        const int s_th = 16 - (i & 15);        // s >= s_th  <=>  j >= cbase
        #pragma unroll
        for (int p = 0; p < 5; ++p) {
            int s = 4*p + g;
            bool val = s < 17;
            int j = lo + (val ? s : 16);
            float sub = (s >= s_th) ? 0.f : 1.0f;
            PAIR_BODY(j, val, sub)
        }
    } else {
        const int n = i + 1;                   // rows 0..15 (all inband, cbase=0)
        for (int p = 0; p < ((n + 3) >> 2); ++p) {
            int s = 4*p + g;
            bool val = s < n;
            int j = val ? s : (n - 1);
            PAIR_BODY(j, val, 0.f)
        }
    }

    // ---- strided taps: t = 1..S (always below cbase -> weight e^x - 1) ----
    {
        const int S = i / 65;
        const int np = (S + 3) >> 2;
        #pragma unroll 2
        for (int p = 0; p < np; ++p) {
            int t = 1 + 4*p + g;
            bool val = t <= S;
            int j = i - 65*(val ? t : S);
            PAIR_BODY(j, val, 1.0f)
        }
    }

    // ---- merge the 4 key groups ----
    accw += __shfl_xor_sync(0xffffffffu, accw, 8);
    accw += __shfl_xor_sync(0xffffffffu, accw, 16);
    a0 = __hadd2(a0, shx2(a0, 8)); a0 = __hadd2(a0, shx2(a0, 16));
    a1 = __hadd2(a1, shx2(a1, 8)); a1 = __hadd2(a1, shx2(a1, 16));
    a2 = __hadd2(a2, shx2(a2, 8)); a2 = __hadd2(a2, shx2(a2, 16));
    a3 = __hadd2(a3, shx2(a3, 8)); a3 = __hadd2(a3, shx2(a3, 16));

    if (g == 0) {
        float inv = __fdividef(1.0f, accw + (float)cbase);
        int cp4 = ((bh>>3)*NCHUNK + (i>>4))*128 + (bh&7)*16 + 2*l8;
        float4 c0 = ((const float4*)g_chunk)[cp4];
        float4 c1 = ((const float4*)g_chunk)[cp4 + 1];
        float2 f0 = __half22float2(a0);
        float2 f1 = __half22float2(a1);
        float2 f2 = __half22float2(a2);
        float2 f3 = __half22float2(a3);
        ((float4*)O)[qoff4] = make_float4((f0.x+c0.x)*inv, (f0.y+c0.y)*inv,
                                          (f1.x+c0.z)*inv, (f1.y+c0.w)*inv);
        ((float4*)O)[qoff4 + 1] = make_float4((f2.x+c1.x)*inv, (f2.y+c1.y)*inv,
                                              (f3.x+c1.z)*inv, (f3.y+c1.w)*inv);
    }
}

// ---------------- Launch -----------------------------------------------------

extern "C" void kernel_launch(void* const* d_in, const int* in_sizes, int n_in,
                              void* d_out, int out_size) {
    const float* Q = (const float*)d_in[0];
    const float* K = (const float*)d_in[1];
    const float* V = (const float*)d_in[2];
    // d_in[3] = attn_mask (causal; structure known at compile time, unused)
    float* O = (float*)d_out;

    prepass<<<1024, 256>>>(K, V);        // V: convert + half-chunk sums; K: convert
    scan_chunks<<<4, 256>>>();           // merge halves + 128-step exclusive scan
    dozer_main<<<4096, 256>>>(Q, O);
}

// round 14
// speedup vs baseline: 1.1803x; 1.1803x over previous
#include <cuda_runtime.h>
#include <cuda_fp16.h>

#define Bc 2
#define Lc 2048
#define Hc 8
#define Dc 64
#define HD 512              // floats per sequence position (H*D)
#define CHUNK 16
#define NCHUNK 128          // Lc / CHUNK
#define NE (Bc*Lc*Hc*Dc)    // 2,097,152 elements

// Scratch (device globals — no allocation allowed)
__device__ float  g_chunk[Bc*NCHUNK*HD];        // chunk V sums -> exclusive prefix
__device__ __half g_kh[NE];                     // fp16 shadow of K (row = 128B = 1 line)
__device__ __half g_vh[NE];                     // fp16 shadow of V

// ---------------- Fused pre-pass: single-read V + MLP-4 K convert ------------

__global__ void prepass(const float* __restrict__ K, const float* __restrict__ V) {
    if (blockIdx.x < 256) {
        // block = (b, chunk c): each V float4 read once -> fp16 + chunk sum
        int b = blockIdx.x >> 7, c = blockIdx.x & 127;
        int col  = threadIdx.x & 127;
        int half = threadIdx.x >> 7;
        int p0 = c*CHUNK + half*8;
        const float4* V4 = (const float4*)V;
        uint2* vh = (uint2*)g_vh;
        float4 s = make_float4(0.f,0.f,0.f,0.f);
        #pragma unroll
        for (int rr = 0; rr < 8; ++rr) {
            int idx = (b*Lc + p0 + rr)*128 + col;
            float4 v = V4[idx];
            s.x += v.x; s.y += v.y; s.z += v.z; s.w += v.w;
            __half2 h0 = __floats2half2_rn(v.x, v.y);
            __half2 h1 = __floats2half2_rn(v.z, v.w);
            uint2 uu; uu.x = *(unsigned*)&h0; uu.y = *(unsigned*)&h1;
            vh[idx] = uu;
        }
        __shared__ float4 sm[128];
        if (half) sm[col] = s;
        __syncthreads();
        if (!half) {
            float4 o = sm[col];
            s.x += o.x; s.y += o.y; s.z += o.z; s.w += o.w;
            ((float4*)g_chunk)[(b*NCHUNK + c)*128 + col] = s;
        }
    } else {
        // K fp16 shadow, 4 float4 per thread (MLP=4)
        int t4 = (blockIdx.x - 256)*256 + threadIdx.x;   // 0..131071
        const float4* K4 = (const float4*)K;
        uint2* kh = (uint2*)g_kh;
        float4 k0 = K4[t4];
        float4 k1 = K4[t4 + 131072];
        float4 k2 = K4[t4 + 262144];
        float4 k3 = K4[t4 + 393216];
        #define CVT_ST(KK, OFF) { \
            __half2 h0 = __floats2half2_rn(KK.x, KK.y); \
            __half2 h1 = __floats2half2_rn(KK.z, KK.w); \
            uint2 uu; uu.x = *(unsigned*)&h0; uu.y = *(unsigned*)&h1; \
            kh[t4 + (OFF)] = uu; }
        CVT_ST(k0, 0) CVT_ST(k1, 131072) CVT_ST(k2, 262144) CVT_ST(k3, 393216)
        #undef CVT_ST
    }
}

// Exclusive scan of the 128 chunk sums per (b, dim512). 1024 threads.
__global__ void scan_chunks() {
    int idx = blockIdx.x*256 + threadIdx.x;
    int b = idx >> 9, d = idx & 511;
    float run = 0.f;
    #pragma unroll 8
    for (int c = 0; c < NCHUNK; ++c) {
        int p = (b*NCHUNK + c)*HD + d;
        float t = g_chunk[p];
        g_chunk[p] = run;                     // exclusive prefix (fp32 exact)
        run += t;
    }
}

// ---------------- Main sparse-attention kernel -------------------------------
// One warp per output row i (32768 warps). 4 key groups x 8 lanes; lane owns
// one 16B uint4 of the 128B fp16 row. Dot in fp16 (HMUL2/HFMA2), 3-shuffle
// butterfly over the 8-lane group; V accumulated in fp16 HFMA2 with dual
// alternating accumulator sets. Unified band loop (no i<16 special path:
// cbase=0 there makes sub=0 automatically). launch_bounds(256,6) -> 42-reg
// cap for 6 blocks/SM (75% occupancy) with state trimmed to fit.
// Prefix trick v2: local keys j >= cbase (= i & ~15) use e^x instead of
// e^x - 1; denominator = accw + cbase; fp32 chunk prefix added in epilogue.
// Balance remap: gw = warp*4096 + block -> every block has equal row mix.

__device__ __forceinline__ __half2 shx2(__half2 v, int m) {
    unsigned u = *reinterpret_cast<unsigned*>(&v);
    u = __shfl_xor_sync(0xffffffffu, u, m);
    return *reinterpret_cast<__half2*>(&u);
}

#define PAIR_BODY(J, VAL, SUB, A0,A1,A2,A3)                                   \
{                                                                             \
    uint4 ku = KH[base_u4 + (J)*64];                                          \
    uint4 vu = VH[base_u4 + (J)*64];                                          \
    __half2 sA = __hmul2(qh0, *(const __half2*)&ku.x);                        \
    sA = __hfma2(qh1, *(const __half2*)&ku.y, sA);                            \
    __half2 sB = __hmul2(qh2, *(const __half2*)&ku.z);                        \
    sB = __hfma2(qh3, *(const __half2*)&ku.w, sB);                            \
    float2 sf = __half22float2(__hadd2(sA, sB));                              \
    float xp = sf.x + sf.y;                                                   \
    xp += __shfl_xor_sync(0xffffffffu, xp, 1);                                \
    xp += __shfl_xor_sync(0xffffffffu, xp, 2);                                \
    xp += __shfl_xor_sync(0xffffffffu, xp, 4);                                \
    float w = (VAL) ? (__expf(0.125f*xp) - (SUB)) : 0.f;                      \
    accw += w;                                                                \
    __half2 wh = __float2half2_rn(w);                                         \
    A0 = __hfma2(wh, *(const __half2*)&vu.x, A0);                             \
    A1 = __hfma2(wh, *(const __half2*)&vu.y, A1);                             \
    A2 = __hfma2(wh, *(const __half2*)&vu.z, A2);                             \
    A3 = __hfma2(wh, *(const __half2*)&vu.w, A3);                             \
}

__global__ __launch_bounds__(256, 6)
void dozer_main(const float* __restrict__ Q, float* __restrict__ O) {
    const int lane = threadIdx.x & 31;
    const int g    = lane >> 3;               // key group (0..3)
    const int l8   = lane & 7;                // 16B dim slice within row

    int gw = (threadIdx.x >> 5)*4096 + blockIdx.x;   // balance remap
    int bh = gw >> 11;
    int i  = gw & 2047;
    int base_f  = (bh>>3)*(Lc*HD) + (bh&7)*Dc;
    int base_u4 = (base_f >> 3) + l8;            // uint4 index into half arrays
    int qoff4   = (base_f >> 2) + i*128 + 2*l8;  // float4 index of lane's 8 dims

    const uint4* __restrict__ KH = (const uint4*)g_kh;
    const uint4* __restrict__ VH = (const uint4*)g_vh;

    float4 qa = ((const float4*)Q)[qoff4];
    float4 qb = ((const float4*)Q)[qoff4 + 1];
    const __half2 qh0 = __floats2half2_rn(qa.x, qa.y);
    const __half2 qh1 = __floats2half2_rn(qa.z, qa.w);
    const __half2 qh2 = __floats2half2_rn(qb.x, qb.y);
    const __half2 qh3 = __floats2half2_rn(qb.z, qb.w);

    const __half2 hz = __float2half2_rn(0.f);
    __half2 oa0 = hz, oa1 = hz, oa2 = hz, oa3 = hz;   // accumulator set A
    __half2 ob0 = hz, ob1 = hz, ob2 = hz, ob3 = hz;   // accumulator set B
    float accw = 0.f;

    const int cbase = i & ~15;                 // chunk start row

    // ---- local band (unified: n = min(i,16)+1 keys ending at i) ----
    {
        const int lo = (i > 16) ? (i - 16) : 0;
        const int n  = i - lo + 1;             // <= 17
        const int np = (n + 3) >> 2;           // <= 5
        #pragma unroll 5
        for (int p = 0; p < np; ++p) {
            int s = 4*p + g;
            bool val = s < n;
            int j = lo + (val ? s : (n - 1));
            float sub = (j >= cbase) ? 0.f : 1.0f;
            if (p & 1) { PAIR_BODY(j, val, sub, ob0,ob1,ob2,ob3) }
            else       { PAIR_BODY(j, val, sub, oa0,oa1,oa2,oa3) }
        }
    }

    // ---- strided taps: t = 1..S (always below cbase -> weight e^x - 1) ----
    {
        const int S = i / 65;
        const int np = (S + 3) >> 2;
        #pragma unroll 4
        for (int p = 0; p < np; ++p) {
            int t = 1 + 4*p + g;
            bool val = t <= S;
            int j = i - 65*(val ? t : S);
            if (p & 1) { PAIR_BODY(j, val, 1.0f, ob0,ob1,ob2,ob3) }
            else       { PAIR_BODY(j, val, 1.0f, oa0,oa1,oa2,oa3) }
        }
    }

    // ---- merge accumulator sets + 4 key groups ----
    oa0 = __hadd2(oa0, ob0); oa1 = __hadd2(oa1, ob1);
    oa2 = __hadd2(oa2, ob2); oa3 = __hadd2(oa3, ob3);

    accw += __shfl_xor_sync(0xffffffffu, accw, 8);
    accw += __shfl_xor_sync(0xffffffffu, accw, 16);
    oa0 = __hadd2(oa0, shx2(oa0, 8)); oa0 = __hadd2(oa0, shx2(oa0, 16));
    oa1 = __hadd2(oa1, shx2(oa1, 8)); oa1 = __hadd2(oa1, shx2(oa1, 16));
    oa2 = __hadd2(oa2, shx2(oa2, 8)); oa2 = __hadd2(oa2, shx2(oa2, 16));
    oa3 = __hadd2(oa3, shx2(oa3, 8)); oa3 = __hadd2(oa3, shx2(oa3, 16));

    if (g == 0) {
        float inv = __fdividef(1.0f, accw + (float)cbase);
        int cp4 = ((bh>>3)*NCHUNK + (i>>4))*128 + (bh&7)*16 + 2*l8;
        float4 c0 = ((const float4*)g_chunk)[cp4];
        float4 c1 = ((const float4*)g_chunk)[cp4 + 1];
        float2 f0 = __half22float2(oa0);
        float2 f1 = __half22float2(oa1);
        float2 f2 = __half22float2(oa2);
        float2 f3 = __half22float2(oa3);
        ((float4*)O)[qoff4] = make_float4((f0.x+c0.x)*inv, (f0.y+c0.y)*inv,
                                          (f1.x+c0.z)*inv, (f1.y+c0.w)*inv);
        ((float4*)O)[qoff4 + 1] = make_float4((f2.x+c1.x)*inv, (f2.y+c1.y)*inv,
                                              (f3.x+c1.z)*inv, (f3.y+c1.w)*inv);
    }
}

// ---------------- Launch -----------------------------------------------------

extern "C" void kernel_launch(void* const* d_in, const int* in_sizes, int n_in,
                              void* d_out, int out_size) {
    const float* Q = (const float*)d_in[0];
    const float* K = (const float*)d_in[1];
    const float* V = (const float*)d_in[2];
    // d_in[3] = attn_mask (causal; structure known at compile time, unused)
    float* O = (float*)d_out;

    prepass<<<256 + 512, 256>>>(K, V);   // V: convert+chunk sums; K: MLP-4 convert
    scan_chunks<<<4, 256>>>();           // 128-step exclusive scan (tiny)
    dozer_main<<<4096, 256>>>(Q, O);
}

// round 15
// speedup vs baseline: 1.2937x; 1.0961x over previous
#include <cuda_runtime.h>
#include <cuda_fp16.h>

#define Bc 2
#define Lc 2048
#define Hc 8
#define Dc 64
#define HD 512              // floats per sequence position (H*D)
#define CHUNK 16
#define NCHUNK 128          // Lc / CHUNK
#define NE (Bc*Lc*Hc*Dc)    // 2,097,152 elements

// Scratch (device globals — no allocation allowed)
__device__ float  g_chunk[Bc*NCHUNK*HD];        // chunk V sums -> exclusive prefix
__device__ __half g_kh[NE];                     // fp16 shadow of K (row = 128B = 1 line)
__device__ __half g_vh[NE];                     // fp16 shadow of V

// ---------------- Fused pre-pass: single-read V + MLP-4 K convert ------------

__global__ void prepass(const float* __restrict__ K, const float* __restrict__ V) {
    if (blockIdx.x < 256) {
        // block = (b, chunk c): each V float4 read once -> fp16 + chunk sum
        int b = blockIdx.x >> 7, c = blockIdx.x & 127;
        int col  = threadIdx.x & 127;
        int half = threadIdx.x >> 7;
        int p0 = c*CHUNK + half*8;
        const float4* V4 = (const float4*)V;
        uint2* vh = (uint2*)g_vh;
        float4 s = make_float4(0.f,0.f,0.f,0.f);
        #pragma unroll
        for (int rr = 0; rr < 8; ++rr) {
            int idx = (b*Lc + p0 + rr)*128 + col;
            float4 v = V4[idx];
            s.x += v.x; s.y += v.y; s.z += v.z; s.w += v.w;
            __half2 h0 = __floats2half2_rn(v.x, v.y);
            __half2 h1 = __floats2half2_rn(v.z, v.w);
            uint2 uu; uu.x = *(unsigned*)&h0; uu.y = *(unsigned*)&h1;
            vh[idx] = uu;
        }
        __shared__ float4 sm[128];
        if (half) sm[col] = s;
        __syncthreads();
        if (!half) {
            float4 o = sm[col];
            s.x += o.x; s.y += o.y; s.z += o.z; s.w += o.w;
            ((float4*)g_chunk)[(b*NCHUNK + c)*128 + col] = s;
        }
    } else {
        // K fp16 shadow, 4 float4 per thread (MLP=4)
        int t4 = (blockIdx.x - 256)*256 + threadIdx.x;   // 0..131071
        const float4* K4 = (const float4*)K;
        uint2* kh = (uint2*)g_kh;
        float4 k0 = K4[t4];
        float4 k1 = K4[t4 + 131072];
        float4 k2 = K4[t4 + 262144];
        float4 k3 = K4[t4 + 393216];
        #define CVT_ST(KK, OFF) { \
            __half2 h0 = __floats2half2_rn(KK.x, KK.y); \
            __half2 h1 = __floats2half2_rn(KK.z, KK.w); \
            uint2 uu; uu.x = *(unsigned*)&h0; uu.y = *(unsigned*)&h1; \
            kh[t4 + (OFF)] = uu; }
        CVT_ST(k0, 0) CVT_ST(k1, 131072) CVT_ST(k2, 262144) CVT_ST(k3, 393216)
        #undef CVT_ST
    }
}

// Exclusive scan of the 128 chunk sums per (b, dim512). 1024 threads.
__global__ void scan_chunks() {
    int idx = blockIdx.x*256 + threadIdx.x;
    int b = idx >> 9, d = idx & 511;
    float run = 0.f;
    #pragma unroll 8
    for (int c = 0; c < NCHUNK; ++c) {
        int p = (b*NCHUNK + c)*HD + d;
        float t = g_chunk[p];
        g_chunk[p] = run;                     // exclusive prefix (fp32 exact)
        run += t;
    }
}

// ---------------- Main sparse-attention kernel -------------------------------
// One warp per output row i (32768 warps; 128-thread blocks for fine-grained
// scheduling). 4 key groups x 8 lanes; lane owns one 16B uint4 of the 128B
// fp16 row. Dot in fp16 (HMUL2/HFMA2), 3-shuffle butterfly over the 8-lane
// group; V accumulated in fp16 HFMA2 with dual alternating accumulator sets.
// Tap loop runs FIRST with an explicit 1-deep prefetch pipeline (clamped
// indices, no branches) to keep MLP high; the band's 5 static bodies then
// overlap the tap tail. Prefix trick v2: local keys j >= cbase use e^x
// instead of e^x - 1; denominator = accw + cbase; fp32 chunk prefix in
// epilogue. Balance remap: all 4 warps of a block carry the same row i.

__device__ __forceinline__ __half2 shx2(__half2 v, int m) {
    unsigned u = *reinterpret_cast<unsigned*>(&v);
    u = __shfl_xor_sync(0xffffffffu, u, m);
    return *reinterpret_cast<__half2*>(&u);
}

// Process a preloaded (ku, vu) pair.
#define PAIR_CORE(KU, VU, VAL, SUB, A0,A1,A2,A3)                              \
{                                                                             \
    __half2 sA = __hmul2(qh0, *(const __half2*)&KU.x);                        \
    sA = __hfma2(qh1, *(const __half2*)&KU.y, sA);                            \
    __half2 sB = __hmul2(qh2, *(const __half2*)&KU.z);                        \
    sB = __hfma2(qh3, *(const __half2*)&KU.w, sB);                            \
    float2 sf = __half22float2(__hadd2(sA, sB));                              \
    float xp = sf.x + sf.y;                                                   \
    xp += __shfl_xor_sync(0xffffffffu, xp, 1);                                \
    xp += __shfl_xor_sync(0xffffffffu, xp, 2);                                \
    xp += __shfl_xor_sync(0xffffffffu, xp, 4);                                \
    float w = (VAL) ? (__expf(0.125f*xp) - (SUB)) : 0.f;                      \
    accw += w;                                                                \
    __half2 wh = __float2half2_rn(w);                                         \
    A0 = __hfma2(wh, *(const __half2*)&VU.x, A0);                             \
    A1 = __hfma2(wh, *(const __half2*)&VU.y, A1);                             \
    A2 = __hfma2(wh, *(const __half2*)&VU.z, A2);                             \
    A3 = __hfma2(wh, *(const __half2*)&VU.w, A3);                             \
}

#define PAIR_BODY(J, VAL, SUB, A0,A1,A2,A3)                                   \
{                                                                             \
    uint4 ku = KH[base_u4 + (J)*64];                                          \
    uint4 vu = VH[base_u4 + (J)*64];                                          \
    PAIR_CORE(ku, vu, VAL, SUB, A0,A1,A2,A3)                                  \
}

__global__ __launch_bounds__(128, 12)
void dozer_main(const float* __restrict__ Q, float* __restrict__ O) {
    const int lane = threadIdx.x & 31;
    const int g    = lane >> 3;               // key group (0..3)
    const int l8   = lane & 7;                // 16B dim slice within row

    int gw = (threadIdx.x >> 5)*8192 + blockIdx.x;   // balance remap (4 warps/blk)
    int bh = gw >> 11;
    int i  = gw & 2047;
    int base_f  = (bh>>3)*(Lc*HD) + (bh&7)*Dc;
    int base_u4 = (base_f >> 3) + l8;            // uint4 index into half arrays
    int qoff4   = (base_f >> 2) + i*128 + 2*l8;  // float4 index of lane's 8 dims

    const uint4* __restrict__ KH = (const uint4*)g_kh;
    const uint4* __restrict__ VH = (const uint4*)g_vh;

    float4 qa = ((const float4*)Q)[qoff4];
    float4 qb = ((const float4*)Q)[qoff4 + 1];
    const __half2 qh0 = __floats2half2_rn(qa.x, qa.y);
    const __half2 qh1 = __floats2half2_rn(qa.z, qa.w);
    const __half2 qh2 = __floats2half2_rn(qb.x, qb.y);
    const __half2 qh3 = __floats2half2_rn(qb.z, qb.w);

    const __half2 hz = __float2half2_rn(0.f);
    __half2 oa0 = hz, oa1 = hz, oa2 = hz, oa3 = hz;   // accumulator set A
    __half2 ob0 = hz, ob1 = hz, ob2 = hz, ob3 = hz;   // accumulator set B
    float accw = 0.f;

    const int cbase = i & ~15;                 // chunk start row

    // ---- strided taps FIRST: t = 1..S, 1-deep prefetch pipeline ----
    {
        const int S = i / 65;
        const int np = (S + 3) >> 2;
        if (np > 0) {
            int t0 = 1 + g;
            uint4 ku = KH[base_u4 + (i - 65*((t0 <= S) ? t0 : S))*64];
            uint4 vu = VH[base_u4 + (i - 65*((t0 <= S) ? t0 : S))*64];
            #pragma unroll 2
            for (int p = 0; p < np; ++p) {
                // prefetch next iteration (clamped index; always safe)
                int tn = 1 + 4*(p+1) + g;
                int jn = i - 65*((tn <= S) ? tn : S);
                uint4 kn = KH[base_u4 + jn*64];
                uint4 vn = VH[base_u4 + jn*64];
                bool val = (1 + 4*p + g) <= S;
                if (p & 1) { PAIR_CORE(ku, vu, val, 1.0f, ob0,ob1,ob2,ob3) }
                else       { PAIR_CORE(ku, vu, val, 1.0f, oa0,oa1,oa2,oa3) }
                ku = kn; vu = vn;
            }
        }
    }

    // ---- local band (R10 structure: static 5 bodies for i >= 16) ----
    if (i >= 16) {
        const int lo = i - 16;                 // 17 keys: 5 batches of 4
        const int s_th = 16 - (i & 15);        // s >= s_th  <=>  j >= cbase
        #pragma unroll
        for (int p = 0; p < 5; ++p) {
            int s = 4*p + g;
            bool val = s < 17;
            int j = lo + (val ? s : 16);
            float sub = (s >= s_th) ? 0.f : 1.0f;
            if (p & 1) { PAIR_BODY(j, val, sub, ob0,ob1,ob2,ob3) }
            else       { PAIR_BODY(j, val, sub, oa0,oa1,oa2,oa3) }
        }
    } else {
        const int n = i + 1;                   // rows 0..15 (cbase = 0: sub = 0)
        for (int p = 0; p < ((n + 3) >> 2); ++p) {
            int s = 4*p + g;
            bool val = s < n;
            int j = val ? s : (n - 1);
            if (p & 1) { PAIR_BODY(j, val, 0.f, ob0,ob1,ob2,ob3) }
            else       { PAIR_BODY(j, val, 0.f, oa0,oa1,oa2,oa3) }
        }
    }

    // ---- merge accumulator sets + 4 key groups ----
    oa0 = __hadd2(oa0, ob0); oa1 = __hadd2(oa1, ob1);
    oa2 = __hadd2(oa2, ob2); oa3 = __hadd2(oa3, ob3);

    accw += __shfl_xor_sync(0xffffffffu, accw, 8);
    accw += __shfl_xor_sync(0xffffffffu, accw, 16);
    oa0 = __hadd2(oa0, shx2(oa0, 8)); oa0 = __hadd2(oa0, shx2(oa0, 16));
    oa1 = __hadd2(oa1, shx2(oa1, 8)); oa1 = __hadd2(oa1, shx2(oa1, 16));
    oa2 = __hadd2(oa2, shx2(oa2, 8)); oa2 = __hadd2(oa2, shx2(oa2, 16));
    oa3 = __hadd2(oa3, shx2(oa3, 8)); oa3 = __hadd2(oa3, shx2(oa3, 16));

    if (g == 0) {
        float inv = __fdividef(1.0f, accw + (float)cbase);
        int cp4 = ((bh>>3)*NCHUNK + (i>>4))*128 + (bh&7)*16 + 2*l8;
        float4 c0 = ((const float4*)g_chunk)[cp4];
        float4 c1 = ((const float4*)g_chunk)[cp4 + 1];
        float2 f0 = __half22float2(oa0);
        float2 f1 = __half22float2(oa1);
        float2 f2 = __half22float2(oa2);
        float2 f3 = __half22float2(oa3);
        ((float4*)O)[qoff4] = make_float4((f0.x+c0.x)*inv, (f0.y+c0.y)*inv,
                                          (f1.x+c0.z)*inv, (f1.y+c0.w)*inv);
        ((float4*)O)[qoff4 + 1] = make_float4((f2.x+c1.x)*inv, (f2.y+c1.y)*inv,
                                              (f3.x+c1.z)*inv, (f3.y+c1.w)*inv);
    }
}

// ---------------- Launch -----------------------------------------------------

extern "C" void kernel_launch(void* const* d_in, const int* in_sizes, int n_in,
                              void* d_out, int out_size) {
    const float* Q = (const float*)d_in[0];
    const float* K = (const float*)d_in[1];
    const float* V = (const float*)d_in[2];
    // d_in[3] = attn_mask (causal; structure known at compile time, unused)
    float* O = (float*)d_out;

    prepass<<<256 + 512, 256>>>(K, V);   // V: convert+chunk sums; K: MLP-4 convert
    scan_chunks<<<4, 256>>>();           // 128-step exclusive scan (tiny)
    dozer_main<<<8192, 128>>>(Q, O);     // 32768 warps, 128-thread blocks
}